// round 3
// baseline (speedup 1.0000x reference)
#include <cuda_runtime.h>
#include <cuda_bf16.h>

// ---------------------------------------------------------------------------
// GAT network: embed -> GAT(H=4) -> GAT(H=4) -> GAT(H=1) -> MLP(64->32->1)
// N=50000, E=800000 (+self loops), HID=64.
// Strategy: CSR by dst built per launch; warp-per-node online-softmax
// aggregation; tiled fp32 SIMT GEMMs for projections.
// ---------------------------------------------------------------------------

#define N_MAX 51200
#define E_MAX 900000

__device__ float g_featA[(size_t)N_MAX * 256];
__device__ float g_featB[(size_t)N_MAX * 256];
__device__ float g_proj [(size_t)N_MAX * 256];
__device__ float g_as[N_MAX * 4];
__device__ float g_ad[N_MAX * 4];
__device__ int   g_off[N_MAX + 1];
__device__ int   g_cur[N_MAX];
__device__ int   g_bsum[64];
__device__ int   g_csr[E_MAX];

// ---------------- CSR build ----------------

__global__ void k_zero_int(int* p, int n) {
    int i = blockIdx.x * blockDim.x + threadIdx.x;
    if (i < n) p[i] = 0;
}

__global__ void k_count_deg(const int* __restrict__ dst, int* __restrict__ deg, int e) {
    int i = blockIdx.x * blockDim.x + threadIdx.x;
    if (i < e) atomicAdd(&deg[dst[i]], 1);
}

// in-place: reads degrees from `buf`, writes exclusive partial scan back, block sums out
__global__ void k_scan1(int* __restrict__ buf, int* __restrict__ bsum, int n) {
    __shared__ int sh[1024];
    int tid = threadIdx.x;
    int i = blockIdx.x * 1024 + tid;
    int v = (i < n) ? buf[i] : 0;
    sh[tid] = v;
    __syncthreads();
    #pragma unroll
    for (int off = 1; off < 1024; off <<= 1) {
        int t = (tid >= off) ? sh[tid - off] : 0;
        __syncthreads();
        sh[tid] += t;
        __syncthreads();
    }
    if (i < n) buf[i] = sh[tid] - v;       // exclusive within block
    if (tid == 1023) bsum[blockIdx.x] = sh[1023];
}

__global__ void k_scan2(int* __restrict__ bsum, int nb) {
    if (threadIdx.x == 0 && blockIdx.x == 0) {
        int run = 0;
        for (int i = 0; i < nb; i++) { int v = bsum[i]; bsum[i] = run; run += v; }
    }
}

__global__ void k_scan3(int* __restrict__ off, const int* __restrict__ bsum,
                        int* __restrict__ cur, int n, int e_total) {
    int i = blockIdx.x * blockDim.x + threadIdx.x;
    if (i < n) {
        int v = off[i] + bsum[i >> 10];
        off[i] = v;
        cur[i] = v;
    }
    if (i == 0) off[n] = e_total;
}

// NOTE: atomic rank assignment makes neighbor ORDER nondeterministic run-to-run.
// This perturbs fp accumulation order (~1e-7 rel), far inside the 1e-3 check.
__global__ void k_scatter(const int* __restrict__ src, const int* __restrict__ dst,
                          int* __restrict__ cur, int* __restrict__ csr, int e) {
    int i = blockIdx.x * blockDim.x + threadIdx.x;
    if (i < e) {
        int pos = atomicAdd(&cur[dst[i]], 1);
        csr[pos] = src[i];
    }
}

// ---------------- GEMM: C[M,N] = A[M,K] @ B[K,N] (+bias, optional relu) -----
// Row-major, K % 16 == 0, N % 64 == 0. Tile 128x64x16, 256 threads, 8x4/thread.

template<bool RELU, bool HAS_BIAS>
__global__ void __launch_bounds__(256)
k_gemm(const float* __restrict__ A, const float* __restrict__ B,
       const float* __restrict__ bias, float* __restrict__ C,
       int M, int N, int K) {
    __shared__ float As[16][128];
    __shared__ float Bs[16][64];
    int tid = threadIdx.x;
    int tx = tid & 15;        // 0..15, 4 cols each
    int ty = tid >> 4;        // 0..15, 8 rows each
    int rowBase = blockIdx.x * 128;
    int colBase = blockIdx.y * 64;

    int ar = tid >> 2;          // 0..63
    int ak = (tid & 3) * 4;     // 0,4,8,12
    int br = tid >> 4;          // 0..15
    int bc = (tid & 15) * 4;    // 0..60

    float acc[8][4];
    #pragma unroll
    for (int i = 0; i < 8; i++)
        #pragma unroll
        for (int j = 0; j < 4; j++) acc[i][j] = 0.f;

    for (int k0 = 0; k0 < K; k0 += 16) {
        #pragma unroll
        for (int half = 0; half < 2; half++) {
            int r = ar + half * 64;
            int grow = rowBase + r;
            float4 v = make_float4(0.f, 0.f, 0.f, 0.f);
            if (grow < M) v = *(const float4*)&A[(size_t)grow * K + k0 + ak];
            As[ak + 0][r] = v.x; As[ak + 1][r] = v.y;
            As[ak + 2][r] = v.z; As[ak + 3][r] = v.w;
        }
        float4 bv = *(const float4*)&B[(size_t)(k0 + br) * N + colBase + bc];
        *(float4*)&Bs[br][bc] = bv;
        __syncthreads();

        #pragma unroll
        for (int k = 0; k < 16; k++) {
            float a[8], b[4];
            #pragma unroll
            for (int i = 0; i < 8; i++) a[i] = As[k][ty * 8 + i];
            #pragma unroll
            for (int j = 0; j < 4; j++) b[j] = Bs[k][tx * 4 + j];
            #pragma unroll
            for (int i = 0; i < 8; i++)
                #pragma unroll
                for (int j = 0; j < 4; j++) acc[i][j] += a[i] * b[j];
        }
        __syncthreads();
    }

    #pragma unroll
    for (int i = 0; i < 8; i++) {
        int r = rowBase + ty * 8 + i;
        if (r >= M) continue;
        #pragma unroll
        for (int j = 0; j < 4; j++) {
            int c = colBase + tx * 4 + j;
            float v = acc[i][j];
            if (HAS_BIAS) v += bias[c];
            if (RELU) v = fmaxf(v, 0.f);
            C[(size_t)r * N + c] = v;
        }
    }
}

// ---------------- attention coefficient dot products -----------------------
// alpha_s[n,h] = dot(hproj[n,h,:], aws[h,:]);  same for awd. Warp per node.

template<int H>
__global__ void __launch_bounds__(256)
k_alpha(const float* __restrict__ hproj,
        const float* __restrict__ aws, const float* __restrict__ awd,
        float* __restrict__ as_out, float* __restrict__ ad_out, int n) {
    int gw = (blockIdx.x * blockDim.x + threadIdx.x) >> 5;
    if (gw >= n) return;
    int lane = threadIdx.x & 31;
    const float* hr = hproj + (size_t)gw * H * 64;
    #pragma unroll
    for (int h = 0; h < H; h++) {
        float v0 = hr[h * 64 + lane];
        float v1 = hr[h * 64 + 32 + lane];
        float ps = v0 * aws[h * 64 + lane] + v1 * aws[h * 64 + 32 + lane];
        float pd = v0 * awd[h * 64 + lane] + v1 * awd[h * 64 + 32 + lane];
        #pragma unroll
        for (int o = 16; o > 0; o >>= 1) {
            ps += __shfl_xor_sync(0xffffffffu, ps, o);
            pd += __shfl_xor_sync(0xffffffffu, pd, o);
        }
        if (lane == 0) {
            as_out[gw * H + h] = ps;
            ad_out[gw * H + h] = pd;
        }
    }
}

// ---------------- aggregation: warp per node, online softmax ---------------

template<int H, bool RELU>
__global__ void __launch_bounds__(256)
k_gat_agg(const float* __restrict__ hproj,
          const float* __restrict__ asrc, const float* __restrict__ adst,
          const int* __restrict__ off, const int* __restrict__ csr,
          const float* __restrict__ bias,
          float* __restrict__ out, int n) {
    constexpr int HC = H * 64;
    constexpr int KPL = HC / 32;
    int gw = (blockIdx.x * blockDim.x + threadIdx.x) >> 5;
    if (gw >= n) return;
    int lane = threadIdx.x & 31;
    int node = gw;

    float adh[H], m[H], s[H];
    #pragma unroll
    for (int h = 0; h < H; h++) {
        adh[h] = adst[node * H + h];
        m[h] = -1e30f;
        s[h] = 0.f;
    }
    float acc[KPL];
    #pragma unroll
    for (int k = 0; k < KPL; k++) acc[k] = 0.f;

    int beg = off[node], end = off[node + 1];
    // e == beg-1 is the implicit self-loop
    for (int e = beg - 1; e < end; e++) {
        int src = (e < beg) ? node : csr[e];
        float w[H], sc[H];
        #pragma unroll
        for (int h = 0; h < H; h++) {
            float ev = asrc[src * H + h] + adh[h];
            ev = ev > 0.f ? ev : 0.2f * ev;           // leaky relu
            float nm = fmaxf(m[h], ev);
            sc[h] = __expf(m[h] - nm);
            w[h]  = __expf(ev - nm);
            s[h]  = s[h] * sc[h] + w[h];
            m[h]  = nm;
        }
        const float* hr = hproj + (size_t)src * HC;
        #pragma unroll
        for (int k = 0; k < KPL; k++) {
            int col = lane + 32 * k;
            int h = col >> 6;
            acc[k] = acc[k] * sc[h] + w[h] * hr[col];
        }
    }

    #pragma unroll
    for (int k = 0; k < KPL; k++) {
        int col = lane + 32 * k;
        int h = col >> 6;
        float v = acc[k] / (s[h] + 1e-16f) + bias[col];
        if (RELU) v = fmaxf(v, 0.f);
        out[(size_t)node * HC + col] = v;
    }
}

// ---------------- final MLP: 64 -> 32 (relu) -> 1, warp per node -----------

__global__ void __launch_bounds__(256)
k_mlp(const float* __restrict__ feat,
      const float* __restrict__ Wo1, const float* __restrict__ bo1,
      const float* __restrict__ Wo2, const float* __restrict__ bo2,
      float* __restrict__ out, int n) {
    int gw = (blockIdx.x * blockDim.x + threadIdx.x) >> 5;
    if (gw >= n) return;
    int lane = threadIdx.x & 31;
    float f0 = feat[(size_t)gw * 64 + lane];
    float f1 = feat[(size_t)gw * 64 + 32 + lane];
    float hid = bo1[lane];
    #pragma unroll
    for (int k = 0; k < 32; k++) {
        float xv = __shfl_sync(0xffffffffu, f0, k);
        hid += xv * Wo1[k * 32 + lane];
    }
    #pragma unroll
    for (int k = 0; k < 32; k++) {
        float xv = __shfl_sync(0xffffffffu, f1, k);
        hid += xv * Wo1[(32 + k) * 32 + lane];
    }
    hid = fmaxf(hid, 0.f);
    float p = hid * Wo2[lane];
    #pragma unroll
    for (int o = 16; o > 0; o >>= 1) p += __shfl_xor_sync(0xffffffffu, p, o);
    if (lane == 0) out[gw] = p + bo2[0];
}

// ---------------------------------------------------------------------------

extern "C" void kernel_launch(void* const* d_in, const int* in_sizes, int n_in,
                              void* d_out, int out_size) {
    const float* x     = (const float*)d_in[0];
    const float* W_emb = (const float*)d_in[1];
    const float* b_emb = (const float*)d_in[2];
    const float* W0    = (const float*)d_in[3];
    const float* as0   = (const float*)d_in[4];
    const float* ad0   = (const float*)d_in[5];
    const float* b0    = (const float*)d_in[6];
    const float* W1    = (const float*)d_in[7];
    const float* as1   = (const float*)d_in[8];
    const float* ad1   = (const float*)d_in[9];
    const float* b1    = (const float*)d_in[10];
    const float* W2    = (const float*)d_in[11];
    const float* as2   = (const float*)d_in[12];
    const float* ad2   = (const float*)d_in[13];
    const float* b2    = (const float*)d_in[14];
    const float* Wo1   = (const float*)d_in[15];
    const float* bo1   = (const float*)d_in[16];
    const float* Wo2   = (const float*)d_in[17];
    const float* bo2   = (const float*)d_in[18];
    const int*   ei    = (const int*)d_in[19];

    int n = in_sizes[0] / 128;
    int E = in_sizes[19] / 2;
    const int* esrc = ei;
    const int* edst = ei + E;

    float *featA, *featB, *proj, *asb, *adb;
    int *off, *cur, *bsum, *csr;
    cudaGetSymbolAddress((void**)&featA, g_featA);
    cudaGetSymbolAddress((void**)&featB, g_featB);
    cudaGetSymbolAddress((void**)&proj,  g_proj);
    cudaGetSymbolAddress((void**)&asb,   g_as);
    cudaGetSymbolAddress((void**)&adb,   g_ad);
    cudaGetSymbolAddress((void**)&off,   g_off);
    cudaGetSymbolAddress((void**)&cur,   g_cur);
    cudaGetSymbolAddress((void**)&bsum,  g_bsum);
    cudaGetSymbolAddress((void**)&csr,   g_csr);

    // ---- CSR build ----
    k_zero_int<<<(n + 1 + 255) / 256, 256>>>(off, n + 1);
    k_count_deg<<<(E + 255) / 256, 256>>>(edst, off, E);
    int nb = (n + 1023) / 1024;
    k_scan1<<<nb, 1024>>>(off, bsum, n);
    k_scan2<<<1, 32>>>(bsum, nb);
    k_scan3<<<(n + 255) / 256, 256>>>(off, bsum, cur, n, E);
    k_scatter<<<(E + 255) / 256, 256>>>(esrc, edst, cur, csr, E);

    dim3 blk(256);
    int warpBlocks = (n + 7) / 8;   // 8 warps / block

    // ---- embed: relu(x @ W_emb + b_emb) -> featA [n,64] ----
    {
        dim3 grid((n + 127) / 128, 64 / 64);
        k_gemm<true, true><<<grid, blk>>>(x, W_emb, b_emb, featA, n, 64, 128);
    }

    // ---- GAT layer 0: featA[n,64] -> featB[n,256] ----
    {
        dim3 grid((n + 127) / 128, 256 / 64);
        k_gemm<false, false><<<grid, blk>>>(featA, W0, nullptr, proj, n, 256, 64);
        k_alpha<4><<<warpBlocks, blk>>>(proj, as0, ad0, asb, adb, n);
        k_gat_agg<4, true><<<warpBlocks, blk>>>(proj, asb, adb, off, csr, b0, featB, n);
    }

    // ---- GAT layer 1: featB[n,256] -> featA[n,256] ----
    {
        dim3 grid((n + 127) / 128, 256 / 64);
        k_gemm<false, false><<<grid, blk>>>(featB, W1, nullptr, proj, n, 256, 256);
        k_alpha<4><<<warpBlocks, blk>>>(proj, as1, ad1, asb, adb, n);
        k_gat_agg<4, true><<<warpBlocks, blk>>>(proj, asb, adb, off, csr, b1, featA, n);
    }

    // ---- GAT layer 2 (H=1, no relu): featA[n,256] -> featB[n,64] ----
    {
        dim3 grid((n + 127) / 128, 64 / 64);
        k_gemm<false, false><<<grid, blk>>>(featA, W2, nullptr, proj, n, 64, 256);
        k_alpha<1><<<warpBlocks, blk>>>(proj, as2, ad2, asb, adb, n);
        k_gat_agg<1, false><<<warpBlocks, blk>>>(proj, asb, adb, off, csr, b2, featB, n);
    }

    // ---- MLP tail -> d_out [n,1] ----
    k_mlp<<<warpBlocks, blk>>>(featB, Wo1, bo1, Wo2, bo2, (float*)d_out, n);
}

// round 9
// speedup vs baseline: 1.2327x; 1.2327x over previous
#include <cuda_runtime.h>
#include <cuda_bf16.h>
#include <cstdint>

// ---------------------------------------------------------------------------
// GAT network: embed -> GAT(H=4) -> GAT(H=4) -> GAT(H=1) -> MLP(64->32->1)
// N=50000, E=800000 (+self loops), HID=64.
// NOTE: harness ptxas targets sm_103 (no 'a') -> tcgen05 unavailable.
// GEMMs use portable mma.sync bf16 (HMMA) with bf16x3 split for fp32 accuracy;
// attention logits fused into the GEMM epilogue. CSR + warp-per-node online
// softmax aggregation.
// ---------------------------------------------------------------------------

#define N_MAX 51200
#define E_MAX 900000

__device__ float g_featA[(size_t)N_MAX * 256];
__device__ float g_featB[(size_t)N_MAX * 256];
__device__ float g_proj [(size_t)N_MAX * 256];
__device__ float g_as[N_MAX * 4];
__device__ float g_ad[N_MAX * 4];
__device__ int   g_off[N_MAX + 1];
__device__ int   g_cur[N_MAX];
__device__ int   g_bsum[64];
__device__ int   g_csr[E_MAX];
__device__ __nv_bfloat16 g_wt_hi[65536];
__device__ __nv_bfloat16 g_wt_lo[65536];

// ---------------- mma.sync m16n8k16 bf16 (fp32 accum), sm_80+ portable ------

__device__ __forceinline__ void mma_bf16(float* c, const uint32_t* a, const uint32_t* b) {
    asm volatile(
        "mma.sync.aligned.m16n8k16.row.col.f32.bf16.bf16.f32 "
        "{%0,%1,%2,%3},{%4,%5,%6,%7},{%8,%9},{%0,%1,%2,%3};\n"
        : "+f"(c[0]), "+f"(c[1]), "+f"(c[2]), "+f"(c[3])
        : "r"(a[0]), "r"(a[1]), "r"(a[2]), "r"(a[3]), "r"(b[0]), "r"(b[1]));
}

// ---------------- W conversion: W[K,N] fp32 -> Wt_hi/lo[N,K] bf16 (split) ----

__global__ void k_cvt_w(const float* __restrict__ W, __nv_bfloat16* __restrict__ hi,
                        __nv_bfloat16* __restrict__ lo, int K, int N) {
    int idx = blockIdx.x * blockDim.x + threadIdx.x;
    if (idx >= K * N) return;
    int k = idx / N, n = idx % N;
    float v = W[idx];
    __nv_bfloat16 h = __float2bfloat16(v);
    float r = v - __bfloat162float(h);
    hi[n * K + k] = h;
    lo[n * K + k] = __float2bfloat16(r);
}

// ---------------- bf16x3 split GEMM via mma.sync ----------------------------
// out[M, NW] tile: rows [bx*128, +128), cols [by*NT, +NT).
// A fp32 [M,K] split inline to bf16 hi/lo; B bf16 [NW,K] hi/lo (from k_cvt_w).
// D += Ah*Bh + Ah*Bl + Al*Bh (Al*Bl ~2^-32, dropped).
// Epilogue: bias+relu (embed) or fused attention logit sums (H>0).
// SMEM rows padded to 36 u32 (144B) -> conflict-free fragment loads.

template<int NT, int H, bool BIAS_RELU>
__global__ void __launch_bounds__(256)
k_mma_gemm(const float* __restrict__ A,
           const __nv_bfloat16* __restrict__ Bh, const __nv_bfloat16* __restrict__ Bl,
           const float* __restrict__ bias,
           const float* __restrict__ aws, const float* __restrict__ awd,
           float* __restrict__ out, float* __restrict__ as_out, float* __restrict__ ad_out,
           int M, int K, int NW) {
    extern __shared__ uint32_t sm32[];
    constexpr int KP32 = 36;                  // u32 per padded 64-col row
    uint32_t* Ah32 = sm32;                    // 128*36 u32
    uint32_t* Al32 = sm32 + 128 * KP32;
    uint32_t* Bh32 = sm32 + 2 * 128 * KP32;
    uint32_t* Bl32 = Bh32 + NT * KP32;

    int tid = threadIdx.x, wid = tid >> 5, lane = tid & 31;
    int rbase = blockIdx.x * 128;
    int colBase = blockIdx.y * NT;
    int qr = lane >> 2;                        // 0..7
    int qc = (lane & 3) * 2;                   // 0,2,4,6
    int wrow = wid * 16;

    constexpr int NTILES = NT / 8;
    float acc[NTILES][4];
    #pragma unroll
    for (int t = 0; t < NTILES; t++)
        #pragma unroll
        for (int j = 0; j < 4; j++) acc[t][j] = 0.f;

    for (int k0 = 0; k0 < K; k0 += 64) {
        // ---- stage B chunk: NT rows x 32 u32 (64 bf16) hi/lo ----
        #pragma unroll
        for (int it = 0; it < NT * 32 / 256; it++) {
            int idx = tid + it * 256;
            int nl = idx >> 5, p = idx & 31;
            int g = (colBase + nl) * K + k0 + p * 2;
            Bh32[nl * KP32 + p] = *(const uint32_t*)&Bh[g];
            Bl32[nl * KP32 + p] = *(const uint32_t*)&Bl[g];
        }
        // ---- stage A chunk: 128 rows x 32 u32, fp32 -> bf16 hi/lo split ----
        #pragma unroll
        for (int it = 0; it < 16; it++) {
            int idx = tid + it * 256;
            int r = idx >> 5, p = idx & 31;
            int grow = rbase + r;
            float2 v = make_float2(0.f, 0.f);
            if (grow < M) v = *(const float2*)&A[(size_t)grow * K + k0 + p * 2];
            __nv_bfloat16 h0 = __float2bfloat16(v.x), h1 = __float2bfloat16(v.y);
            __nv_bfloat16 l0 = __float2bfloat16(v.x - __bfloat162float(h0));
            __nv_bfloat16 l1 = __float2bfloat16(v.y - __bfloat162float(h1));
            Ah32[r * KP32 + p] = (uint32_t)__bfloat16_as_ushort(h0) |
                                 ((uint32_t)__bfloat16_as_ushort(h1) << 16);
            Al32[r * KP32 + p] = (uint32_t)__bfloat16_as_ushort(l0) |
                                 ((uint32_t)__bfloat16_as_ushort(l1) << 16);
        }
        __syncthreads();

        #pragma unroll
        for (int ks = 0; ks < 4; ks++) {
            int abase = (wrow + qr) * KP32 + (lane & 3) + ks * 8;
            uint32_t ah[4], al[4];
            ah[0] = Ah32[abase];              al[0] = Al32[abase];
            ah[1] = Ah32[abase + 8 * KP32];   al[1] = Al32[abase + 8 * KP32];
            ah[2] = Ah32[abase + 4];          al[2] = Al32[abase + 4];
            ah[3] = Ah32[abase + 8 * KP32 + 4]; al[3] = Al32[abase + 8 * KP32 + 4];
            #pragma unroll
            for (int nt = 0; nt < NTILES; nt++) {
                int bbase = (nt * 8 + qr) * KP32 + (lane & 3) + ks * 8;
                uint32_t bh[2], bl[2];
                bh[0] = Bh32[bbase]; bh[1] = Bh32[bbase + 4];
                bl[0] = Bl32[bbase]; bl[1] = Bl32[bbase + 4];
                mma_bf16(acc[nt], ah, bh);
                mma_bf16(acc[nt], ah, bl);
                mma_bf16(acc[nt], al, bh);
            }
        }
        __syncthreads();
    }

    // ---- epilogue: fragment rows l/4 and l/4+8, cols nt*8 + qc,+1 ----
    int row_lo = rbase + wrow + qr;
    int row_hi = row_lo + 8;
    constexpr int NH = (H > 0) ? (NT / 64) : 1;
    float aL[NH], aH[NH], dL[NH], dH[NH];
    #pragma unroll
    for (int h = 0; h < NH; h++) { aL[h] = aH[h] = dL[h] = dH[h] = 0.f; }

    #pragma unroll
    for (int nt = 0; nt < NTILES; nt++) {
        int col = nt * 8 + qc;
        int gcol = colBase + col;
        float c0 = acc[nt][0], c1 = acc[nt][1], c2 = acc[nt][2], c3 = acc[nt][3];
        if (BIAS_RELU) {
            float b0 = bias[gcol], b1 = bias[gcol + 1];
            c0 = fmaxf(c0 + b0, 0.f); c1 = fmaxf(c1 + b1, 0.f);
            c2 = fmaxf(c2 + b0, 0.f); c3 = fmaxf(c3 + b1, 0.f);
        }
        if (H > 0) {
            int hl = col >> 6;
            float w0 = aws[gcol], w1 = aws[gcol + 1];
            float u0 = awd[gcol], u1 = awd[gcol + 1];
            aL[hl] += c0 * w0 + c1 * w1;
            aH[hl] += c2 * w0 + c3 * w1;
            dL[hl] += c0 * u0 + c1 * u1;
            dH[hl] += c2 * u0 + c3 * u1;
        }
        if (row_lo < M) *(float2*)&out[(size_t)row_lo * NW + gcol] = make_float2(c0, c1);
        if (row_hi < M) *(float2*)&out[(size_t)row_hi * NW + gcol] = make_float2(c2, c3);
    }

    if (H > 0) {
        #pragma unroll
        for (int h = 0; h < NH; h++) {
            aL[h] += __shfl_xor_sync(0xffffffffu, aL[h], 1);
            aL[h] += __shfl_xor_sync(0xffffffffu, aL[h], 2);
            aH[h] += __shfl_xor_sync(0xffffffffu, aH[h], 1);
            aH[h] += __shfl_xor_sync(0xffffffffu, aH[h], 2);
            dL[h] += __shfl_xor_sync(0xffffffffu, dL[h], 1);
            dL[h] += __shfl_xor_sync(0xffffffffu, dL[h], 2);
            dH[h] += __shfl_xor_sync(0xffffffffu, dH[h], 1);
            dH[h] += __shfl_xor_sync(0xffffffffu, dH[h], 2);
        }
        if ((lane & 3) == 0) {
            #pragma unroll
            for (int h = 0; h < NH; h++) {
                int gh = (colBase >> 6) + h;
                if (row_lo < M) { as_out[row_lo * H + gh] = aL[h]; ad_out[row_lo * H + gh] = dL[h]; }
                if (row_hi < M) { as_out[row_hi * H + gh] = aH[h]; ad_out[row_hi * H + gh] = dH[h]; }
            }
        }
    }
}

// ---------------- CSR build ----------------

__global__ void k_zero_int(int* p, int n) {
    int i = blockIdx.x * blockDim.x + threadIdx.x;
    if (i < n) p[i] = 0;
}

__global__ void k_count_deg(const int* __restrict__ dst, int* __restrict__ deg, int e) {
    int i = blockIdx.x * blockDim.x + threadIdx.x;
    if (i < e) atomicAdd(&deg[dst[i]], 1);
}

__global__ void k_scan1(int* __restrict__ buf, int* __restrict__ bsum, int n) {
    __shared__ int sh[1024];
    int tid = threadIdx.x;
    int i = blockIdx.x * 1024 + tid;
    int v = (i < n) ? buf[i] : 0;
    sh[tid] = v;
    __syncthreads();
    #pragma unroll
    for (int off = 1; off < 1024; off <<= 1) {
        int t = (tid >= off) ? sh[tid - off] : 0;
        __syncthreads();
        sh[tid] += t;
        __syncthreads();
    }
    if (i < n) buf[i] = sh[tid] - v;
    if (tid == 1023) bsum[blockIdx.x] = sh[1023];
}

__global__ void k_scan2(int* __restrict__ bsum, int nb) {
    if (threadIdx.x == 0 && blockIdx.x == 0) {
        int run = 0;
        for (int i = 0; i < nb; i++) { int v = bsum[i]; bsum[i] = run; run += v; }
    }
}

__global__ void k_scan3(int* __restrict__ off, const int* __restrict__ bsum,
                        int* __restrict__ cur, int n, int e_total) {
    int i = blockIdx.x * blockDim.x + threadIdx.x;
    if (i < n) {
        int v = off[i] + bsum[i >> 10];
        off[i] = v;
        cur[i] = v;
    }
    if (i == 0) off[n] = e_total;
}

__global__ void k_scatter(const int* __restrict__ src, const int* __restrict__ dst,
                          int* __restrict__ cur, int* __restrict__ csr, int e) {
    int i = blockIdx.x * blockDim.x + threadIdx.x;
    if (i < e) {
        int pos = atomicAdd(&cur[dst[i]], 1);
        csr[pos] = src[i];
    }
}

// ---------------- aggregation: warp per node, online softmax ---------------

template<int H, bool RELU>
__global__ void __launch_bounds__(256)
k_gat_agg(const float* __restrict__ hproj,
          const float* __restrict__ asrc, const float* __restrict__ adst,
          const int* __restrict__ off, const int* __restrict__ csr,
          const float* __restrict__ bias,
          float* __restrict__ out, int n) {
    constexpr int HC = H * 64;
    constexpr int KPL = HC / 32;
    int gw = (blockIdx.x * blockDim.x + threadIdx.x) >> 5;
    if (gw >= n) return;
    int lane = threadIdx.x & 31;
    int node = gw;

    float adh[H], m[H], s[H];
    #pragma unroll
    for (int h = 0; h < H; h++) {
        adh[h] = adst[node * H + h];
        m[h] = -1e30f;
        s[h] = 0.f;
    }
    float acc[KPL];
    #pragma unroll
    for (int k = 0; k < KPL; k++) acc[k] = 0.f;

    int beg = off[node], end = off[node + 1];
    for (int e = beg - 1; e < end; e++) {
        int src = (e < beg) ? node : csr[e];      // beg-1 == implicit self loop
        float w[H], sc[H];
        #pragma unroll
        for (int h = 0; h < H; h++) {
            float ev = asrc[src * H + h] + adh[h];
            ev = ev > 0.f ? ev : 0.2f * ev;
            float nm = fmaxf(m[h], ev);
            sc[h] = __expf(m[h] - nm);
            w[h]  = __expf(ev - nm);
            s[h]  = s[h] * sc[h] + w[h];
            m[h]  = nm;
        }
        const float* hr = hproj + (size_t)src * HC;
        #pragma unroll
        for (int k = 0; k < KPL; k++) {
            int col = lane + 32 * k;
            int h = col >> 6;
            acc[k] = acc[k] * sc[h] + w[h] * hr[col];
        }
    }

    #pragma unroll
    for (int k = 0; k < KPL; k++) {
        int col = lane + 32 * k;
        int h = col >> 6;
        float v = acc[k] / (s[h] + 1e-16f) + bias[col];
        if (RELU) v = fmaxf(v, 0.f);
        out[(size_t)node * HC + col] = v;
    }
}

// ---------------- final MLP: 64 -> 32 (relu) -> 1, warp per node -----------

__global__ void __launch_bounds__(256)
k_mlp(const float* __restrict__ feat,
      const float* __restrict__ Wo1, const float* __restrict__ bo1,
      const float* __restrict__ Wo2, const float* __restrict__ bo2,
      float* __restrict__ out, int n) {
    int gw = (blockIdx.x * blockDim.x + threadIdx.x) >> 5;
    if (gw >= n) return;
    int lane = threadIdx.x & 31;
    float f0 = feat[(size_t)gw * 64 + lane];
    float f1 = feat[(size_t)gw * 64 + 32 + lane];
    float hid = bo1[lane];
    #pragma unroll
    for (int k = 0; k < 32; k++) {
        float xv = __shfl_sync(0xffffffffu, f0, k);
        hid += xv * Wo1[k * 32 + lane];
    }
    #pragma unroll
    for (int k = 0; k < 32; k++) {
        float xv = __shfl_sync(0xffffffffu, f1, k);
        hid += xv * Wo1[(32 + k) * 32 + lane];
    }
    hid = fmaxf(hid, 0.f);
    float p = hid * Wo2[lane];
    #pragma unroll
    for (int o = 16; o > 0; o >>= 1) p += __shfl_xor_sync(0xffffffffu, p, o);
    if (lane == 0) out[gw] = p + bo2[0];
}

// ---------------------------------------------------------------------------

extern "C" void kernel_launch(void* const* d_in, const int* in_sizes, int n_in,
                              void* d_out, int out_size) {
    const float* x     = (const float*)d_in[0];
    const float* W_emb = (const float*)d_in[1];
    const float* b_emb = (const float*)d_in[2];
    const float* W0    = (const float*)d_in[3];
    const float* as0   = (const float*)d_in[4];
    const float* ad0   = (const float*)d_in[5];
    const float* b0    = (const float*)d_in[6];
    const float* W1    = (const float*)d_in[7];
    const float* as1   = (const float*)d_in[8];
    const float* ad1   = (const float*)d_in[9];
    const float* b1    = (const float*)d_in[10];
    const float* W2    = (const float*)d_in[11];
    const float* as2   = (const float*)d_in[12];
    const float* ad2   = (const float*)d_in[13];
    const float* b2    = (const float*)d_in[14];
    const float* Wo1   = (const float*)d_in[15];
    const float* bo1   = (const float*)d_in[16];
    const float* Wo2   = (const float*)d_in[17];
    const float* bo2   = (const float*)d_in[18];
    const int*   ei    = (const int*)d_in[19];

    int n = in_sizes[0] / 128;
    int E = in_sizes[19] / 2;
    const int* esrc = ei;
    const int* edst = ei + E;

    float *featA, *featB, *proj, *asb, *adb;
    int *off, *cur, *bsum, *csr;
    __nv_bfloat16 *wth, *wtl;
    cudaGetSymbolAddress((void**)&featA, g_featA);
    cudaGetSymbolAddress((void**)&featB, g_featB);
    cudaGetSymbolAddress((void**)&proj,  g_proj);
    cudaGetSymbolAddress((void**)&asb,   g_as);
    cudaGetSymbolAddress((void**)&adb,   g_ad);
    cudaGetSymbolAddress((void**)&off,   g_off);
    cudaGetSymbolAddress((void**)&cur,   g_cur);
    cudaGetSymbolAddress((void**)&bsum,  g_bsum);
    cudaGetSymbolAddress((void**)&csr,   g_csr);
    cudaGetSymbolAddress((void**)&wth,   g_wt_hi);
    cudaGetSymbolAddress((void**)&wtl,   g_wt_lo);

    // dynamic smem: 2*128*36 u32 (A) + 2*NT*36 u32 (B)
    constexpr int SMEM64  = (2 * 128 * 36 + 2 * 64 * 36) * 4;   // 55296
    constexpr int SMEM128 = (2 * 128 * 36 + 2 * 128 * 36) * 4;  // 73728
    cudaFuncSetAttribute(k_mma_gemm<64, 0, true>,   cudaFuncAttributeMaxDynamicSharedMemorySize, SMEM64);
    cudaFuncSetAttribute(k_mma_gemm<128, 4, false>, cudaFuncAttributeMaxDynamicSharedMemorySize, SMEM128);
    cudaFuncSetAttribute(k_mma_gemm<64, 1, false>,  cudaFuncAttributeMaxDynamicSharedMemorySize, SMEM64);

    dim3 blk(256);
    int gemmBlocks = (n + 127) / 128;
    int warpBlocks = (n + 7) / 8;
    int nb = (n + 1023) / 1024;

    // Launch order keeps the proj0 GEMM at index 5 (= ncu -s 5 -c 1 slot).

    // (0) embed W convert, (1) embed GEMM -> featA [n,64]
    k_cvt_w<<<(128 * 64 + 255) / 256, blk>>>(W_emb, wth, wtl, 128, 64);
    k_mma_gemm<64, 0, true><<<dim3(gemmBlocks, 1), blk, SMEM64>>>(
        x, wth, wtl, b_emb, nullptr, nullptr, featA, nullptr, nullptr, n, 128, 64);

    // (2) W0 convert, (3-4) CSR start, (5) proj0 GEMM + fused alpha
    k_cvt_w<<<(64 * 256 + 255) / 256, blk>>>(W0, wth, wtl, 64, 256);
    k_zero_int<<<(n + 1 + 255) / 256, 256>>>(off, n + 1);
    k_count_deg<<<(E + 255) / 256, 256>>>(edst, off, E);
    k_mma_gemm<128, 4, false><<<dim3(gemmBlocks, 2), blk, SMEM128>>>(
        featA, wth, wtl, nullptr, as0, ad0, proj, asb, adb, n, 64, 256);

    // (6-9) CSR finish
    k_scan1<<<nb, 1024>>>(off, bsum, n);
    k_scan2<<<1, 32>>>(bsum, nb);
    k_scan3<<<(n + 255) / 256, 256>>>(off, bsum, cur, n, E);
    k_scatter<<<(E + 255) / 256, 256>>>(esrc, edst, cur, csr, E);

    // (10) agg0 -> featB[n,256]
    k_gat_agg<4, true><<<warpBlocks, blk>>>(proj, asb, adb, off, csr, b0, featB, n);

    // layer 1: featB @ W1 -> proj, agg -> featA
    k_cvt_w<<<(256 * 256 + 255) / 256, blk>>>(W1, wth, wtl, 256, 256);
    k_mma_gemm<128, 4, false><<<dim3(gemmBlocks, 2), blk, SMEM128>>>(
        featB, wth, wtl, nullptr, as1, ad1, proj, asb, adb, n, 256, 256);
    k_gat_agg<4, true><<<warpBlocks, blk>>>(proj, asb, adb, off, csr, b1, featA, n);

    // layer 2 (H=1, no relu): featA @ W2 -> proj[n,64], agg -> featB
    k_cvt_w<<<(256 * 64 + 255) / 256, blk>>>(W2, wth, wtl, 256, 64);
    k_mma_gemm<64, 1, false><<<dim3(gemmBlocks, 1), blk, SMEM64>>>(
        featA, wth, wtl, nullptr, as2, ad2, proj, asb, adb, n, 256, 64);
    k_gat_agg<1, false><<<warpBlocks, blk>>>(proj, asb, adb, off, csr, b2, featB, n);

    // MLP tail -> d_out [n,1]
    k_mlp<<<warpBlocks, blk>>>(featB, Wo1, bo1, Wo2, bo2, (float*)d_out, n);
}

// round 13
// speedup vs baseline: 1.2581x; 1.0206x over previous
#include <cuda_runtime.h>
#include <cuda_bf16.h>
#include <cstdint>

// ---------------------------------------------------------------------------
// GAT network: embed -> GAT(H=4) -> GAT(H=4) -> GAT(H=1) -> MLP(64->32->1)
// N=50000, E=800000 (+self loops), HID=64.
// sm_103 toolchain (no 'a'): tcgen05 unavailable -> portable mma.sync bf16
// (HMMA) with bf16x3 split for fp32 accuracy; attention logits fused into the
// GEMM epilogue. CSR + warp-per-node online-softmax aggregation, float4
// vectorized + 1-edge software pipeline.
// ---------------------------------------------------------------------------

#define N_MAX 51200
#define E_MAX 900000

__device__ float g_featA[(size_t)N_MAX * 256];
__device__ float g_featB[(size_t)N_MAX * 256];
__device__ float g_proj [(size_t)N_MAX * 256];
__device__ float g_as[N_MAX * 4];
__device__ float g_ad[N_MAX * 4];
__device__ int   g_off[N_MAX + 1];
__device__ int   g_cur[N_MAX];
__device__ int   g_bsum[64];
__device__ int   g_csr[E_MAX];
__device__ __nv_bfloat16 g_wt_hi[65536];
__device__ __nv_bfloat16 g_wt_lo[65536];

// ---------------- mma.sync m16n8k16 bf16 (fp32 accum), sm_80+ portable ------

__device__ __forceinline__ void mma_bf16(float* c, const uint32_t* a, const uint32_t* b) {
    asm volatile(
        "mma.sync.aligned.m16n8k16.row.col.f32.bf16.bf16.f32 "
        "{%0,%1,%2,%3},{%4,%5,%6,%7},{%8,%9},{%0,%1,%2,%3};\n"
        : "+f"(c[0]), "+f"(c[1]), "+f"(c[2]), "+f"(c[3])
        : "r"(a[0]), "r"(a[1]), "r"(a[2]), "r"(a[3]), "r"(b[0]), "r"(b[1]));
}

// ---------------- W conversion: W[K,N] fp32 -> Wt_hi/lo[N,K] bf16 (split) ----

__global__ void k_cvt_w(const float* __restrict__ W, __nv_bfloat16* __restrict__ hi,
                        __nv_bfloat16* __restrict__ lo, int K, int N) {
    int idx = blockIdx.x * blockDim.x + threadIdx.x;
    if (idx >= K * N) return;
    int k = idx / N, n = idx % N;
    float v = W[idx];
    __nv_bfloat16 h = __float2bfloat16(v);
    float r = v - __bfloat162float(h);
    hi[n * K + k] = h;
    lo[n * K + k] = __float2bfloat16(r);
}

// ---------------- bf16x3 split GEMM via mma.sync ----------------------------

template<int NT, int H, bool BIAS_RELU>
__global__ void __launch_bounds__(256)
k_mma_gemm(const float* __restrict__ A,
           const __nv_bfloat16* __restrict__ Bh, const __nv_bfloat16* __restrict__ Bl,
           const float* __restrict__ bias,
           const float* __restrict__ aws, const float* __restrict__ awd,
           float* __restrict__ out, float* __restrict__ as_out, float* __restrict__ ad_out,
           int M, int K, int NW) {
    extern __shared__ uint32_t sm32[];
    constexpr int KP32 = 36;                  // u32 per padded 64-col row
    uint32_t* Ah32 = sm32;                    // 128*36 u32
    uint32_t* Al32 = sm32 + 128 * KP32;
    uint32_t* Bh32 = sm32 + 2 * 128 * KP32;
    uint32_t* Bl32 = Bh32 + NT * KP32;

    int tid = threadIdx.x, wid = tid >> 5, lane = tid & 31;
    int rbase = blockIdx.x * 128;
    int colBase = blockIdx.y * NT;
    int qr = lane >> 2;                        // 0..7
    int qc = (lane & 3) * 2;                   // 0,2,4,6
    int wrow = wid * 16;

    constexpr int NTILES = NT / 8;
    float acc[NTILES][4];
    #pragma unroll
    for (int t = 0; t < NTILES; t++)
        #pragma unroll
        for (int j = 0; j < 4; j++) acc[t][j] = 0.f;

    for (int k0 = 0; k0 < K; k0 += 64) {
        #pragma unroll
        for (int it = 0; it < NT * 32 / 256; it++) {
            int idx = tid + it * 256;
            int nl = idx >> 5, p = idx & 31;
            int g = (colBase + nl) * K + k0 + p * 2;
            Bh32[nl * KP32 + p] = *(const uint32_t*)&Bh[g];
            Bl32[nl * KP32 + p] = *(const uint32_t*)&Bl[g];
        }
        #pragma unroll
        for (int it = 0; it < 16; it++) {
            int idx = tid + it * 256;
            int r = idx >> 5, p = idx & 31;
            int grow = rbase + r;
            float2 v = make_float2(0.f, 0.f);
            if (grow < M) v = *(const float2*)&A[(size_t)grow * K + k0 + p * 2];
            __nv_bfloat16 h0 = __float2bfloat16(v.x), h1 = __float2bfloat16(v.y);
            __nv_bfloat16 l0 = __float2bfloat16(v.x - __bfloat162float(h0));
            __nv_bfloat16 l1 = __float2bfloat16(v.y - __bfloat162float(h1));
            Ah32[r * KP32 + p] = (uint32_t)__bfloat16_as_ushort(h0) |
                                 ((uint32_t)__bfloat16_as_ushort(h1) << 16);
            Al32[r * KP32 + p] = (uint32_t)__bfloat16_as_ushort(l0) |
                                 ((uint32_t)__bfloat16_as_ushort(l1) << 16);
        }
        __syncthreads();

        #pragma unroll
        for (int ks = 0; ks < 4; ks++) {
            int abase = (wrow + qr) * KP32 + (lane & 3) + ks * 8;
            uint32_t ah[4], al[4];
            ah[0] = Ah32[abase];                al[0] = Al32[abase];
            ah[1] = Ah32[abase + 8 * KP32];     al[1] = Al32[abase + 8 * KP32];
            ah[2] = Ah32[abase + 4];            al[2] = Al32[abase + 4];
            ah[3] = Ah32[abase + 8 * KP32 + 4]; al[3] = Al32[abase + 8 * KP32 + 4];
            #pragma unroll
            for (int nt = 0; nt < NTILES; nt++) {
                int bbase = (nt * 8 + qr) * KP32 + (lane & 3) + ks * 8;
                uint32_t bh[2], bl[2];
                bh[0] = Bh32[bbase]; bh[1] = Bh32[bbase + 4];
                bl[0] = Bl32[bbase]; bl[1] = Bl32[bbase + 4];
                mma_bf16(acc[nt], ah, bh);
                mma_bf16(acc[nt], ah, bl);
                mma_bf16(acc[nt], al, bh);
            }
        }
        __syncthreads();
    }

    int row_lo = rbase + wrow + qr;
    int row_hi = row_lo + 8;
    constexpr int NH = (H > 0) ? (NT / 64) : 1;
    float aL[NH], aH[NH], dL[NH], dH[NH];
    #pragma unroll
    for (int h = 0; h < NH; h++) { aL[h] = aH[h] = dL[h] = dH[h] = 0.f; }

    #pragma unroll
    for (int nt = 0; nt < NTILES; nt++) {
        int col = nt * 8 + qc;
        int gcol = colBase + col;
        float c0 = acc[nt][0], c1 = acc[nt][1], c2 = acc[nt][2], c3 = acc[nt][3];
        if (BIAS_RELU) {
            float b0 = bias[gcol], b1 = bias[gcol + 1];
            c0 = fmaxf(c0 + b0, 0.f); c1 = fmaxf(c1 + b1, 0.f);
            c2 = fmaxf(c2 + b0, 0.f); c3 = fmaxf(c3 + b1, 0.f);
        }
        if (H > 0) {
            int hl = col >> 6;
            float w0 = aws[gcol], w1 = aws[gcol + 1];
            float u0 = awd[gcol], u1 = awd[gcol + 1];
            aL[hl] += c0 * w0 + c1 * w1;
            aH[hl] += c2 * w0 + c3 * w1;
            dL[hl] += c0 * u0 + c1 * u1;
            dH[hl] += c2 * u0 + c3 * u1;
        }
        if (row_lo < M) *(float2*)&out[(size_t)row_lo * NW + gcol] = make_float2(c0, c1);
        if (row_hi < M) *(float2*)&out[(size_t)row_hi * NW + gcol] = make_float2(c2, c3);
    }

    if (H > 0) {
        #pragma unroll
        for (int h = 0; h < NH; h++) {
            aL[h] += __shfl_xor_sync(0xffffffffu, aL[h], 1);
            aL[h] += __shfl_xor_sync(0xffffffffu, aL[h], 2);
            aH[h] += __shfl_xor_sync(0xffffffffu, aH[h], 1);
            aH[h] += __shfl_xor_sync(0xffffffffu, aH[h], 2);
            dL[h] += __shfl_xor_sync(0xffffffffu, dL[h], 1);
            dL[h] += __shfl_xor_sync(0xffffffffu, dL[h], 2);
            dH[h] += __shfl_xor_sync(0xffffffffu, dH[h], 1);
            dH[h] += __shfl_xor_sync(0xffffffffu, dH[h], 2);
        }
        if ((lane & 3) == 0) {
            #pragma unroll
            for (int h = 0; h < NH; h++) {
                int gh = (colBase >> 6) + h;
                if (row_lo < M) { as_out[row_lo * H + gh] = aL[h]; ad_out[row_lo * H + gh] = dL[h]; }
                if (row_hi < M) { as_out[row_hi * H + gh] = aH[h]; ad_out[row_hi * H + gh] = dH[h]; }
            }
        }
    }
}

// ---------------- CSR build ----------------

__global__ void k_zero_int(int* p, int n) {
    int i = blockIdx.x * blockDim.x + threadIdx.x;
    if (i < n) p[i] = 0;
}

__global__ void k_count_deg(const int* __restrict__ dst, int* __restrict__ deg, int e) {
    int i = blockIdx.x * blockDim.x + threadIdx.x;
    if (i < e) atomicAdd(&deg[dst[i]], 1);
}

__global__ void k_scan1(int* __restrict__ buf, int* __restrict__ bsum, int n) {
    __shared__ int sh[1024];
    int tid = threadIdx.x;
    int i = blockIdx.x * 1024 + tid;
    int v = (i < n) ? buf[i] : 0;
    sh[tid] = v;
    __syncthreads();
    #pragma unroll
    for (int off = 1; off < 1024; off <<= 1) {
        int t = (tid >= off) ? sh[tid - off] : 0;
        __syncthreads();
        sh[tid] += t;
        __syncthreads();
    }
    if (i < n) buf[i] = sh[tid] - v;
    if (tid == 1023) bsum[blockIdx.x] = sh[1023];
}

__global__ void k_scan2(int* __restrict__ bsum, int nb) {
    if (threadIdx.x == 0 && blockIdx.x == 0) {
        int run = 0;
        for (int i = 0; i < nb; i++) { int v = bsum[i]; bsum[i] = run; run += v; }
    }
}

__global__ void k_scan3(int* __restrict__ off, const int* __restrict__ bsum,
                        int* __restrict__ cur, int n, int e_total) {
    int i = blockIdx.x * blockDim.x + threadIdx.x;
    if (i < n) {
        int v = off[i] + bsum[i >> 10];
        off[i] = v;
        cur[i] = v;
    }
    if (i == 0) off[n] = e_total;
}

__global__ void k_scatter(const int* __restrict__ src, const int* __restrict__ dst,
                          int* __restrict__ cur, int* __restrict__ csr, int e) {
    int i = blockIdx.x * blockDim.x + threadIdx.x;
    if (i < e) {
        int pos = atomicAdd(&cur[dst[i]], 1);
        csr[pos] = src[i];
    }
}

// ---------------- aggregation H=4: warp/node, online softmax, pipelined -----
// Per lane: acc0 = cols [lane*4, +4) (head lane>>4), acc1 = cols 128+lane*4
// (head 2+(lane>>4)). Next edge's src/alpha/features loaded before computing
// the current edge (2-stage pipeline).

__global__ void __launch_bounds__(256)
k_agg4(const float* __restrict__ hproj,
       const float* __restrict__ asrc, const float* __restrict__ adst,
       const int* __restrict__ off, const int* __restrict__ csr,
       const float* __restrict__ bias, float* __restrict__ out, int n) {
    int gw = (blockIdx.x * blockDim.x + threadIdx.x) >> 5;
    if (gw >= n) return;
    int lane = threadIdx.x & 31;
    int hsel = lane >> 4;                     // 0 or 1

    float4 adh = *(const float4*)&adst[gw * 4];
    float m0 = -1e30f, m1 = -1e30f, m2 = -1e30f, m3 = -1e30f;
    float s0 = 0.f, s1 = 0.f, s2 = 0.f, s3 = 0.f;
    float4 acc0 = make_float4(0.f, 0.f, 0.f, 0.f);
    float4 acc1 = make_float4(0.f, 0.f, 0.f, 0.f);

    int beg = off[gw], end = off[gw + 1];

    // stage 0: self loop
    float4 a4 = *(const float4*)&asrc[gw * 4];
    const float4* hr4 = (const float4*)(hproj + (size_t)gw * 256);
    float4 f0 = hr4[lane], f1 = hr4[lane + 32];

    for (int e = beg; ; e++) {
        bool have_next = e < end;
        int srcn = 0;
        float4 a4n, f0n, f1n;
        if (have_next) {
            srcn = csr[e];
            a4n = *(const float4*)&asrc[srcn * 4];
            const float4* hn = (const float4*)(hproj + (size_t)srcn * 256);
            f0n = hn[lane];
            f1n = hn[lane + 32];
        }

        // compute current edge
        float e0 = a4.x + adh.x; e0 = e0 > 0.f ? e0 : 0.2f * e0;
        float e1 = a4.y + adh.y; e1 = e1 > 0.f ? e1 : 0.2f * e1;
        float e2 = a4.z + adh.z; e2 = e2 > 0.f ? e2 : 0.2f * e2;
        float e3 = a4.w + adh.w; e3 = e3 > 0.f ? e3 : 0.2f * e3;
        float nm0 = fmaxf(m0, e0), nm1 = fmaxf(m1, e1);
        float nm2 = fmaxf(m2, e2), nm3 = fmaxf(m3, e3);
        float sc0 = __expf(m0 - nm0), sc1 = __expf(m1 - nm1);
        float sc2 = __expf(m2 - nm2), sc3 = __expf(m3 - nm3);
        float w0 = __expf(e0 - nm0), w1 = __expf(e1 - nm1);
        float w2 = __expf(e2 - nm2), w3 = __expf(e3 - nm3);
        s0 = s0 * sc0 + w0; s1 = s1 * sc1 + w1;
        s2 = s2 * sc2 + w2; s3 = s3 * sc3 + w3;
        m0 = nm0; m1 = nm1; m2 = nm2; m3 = nm3;

        float scA = hsel ? sc1 : sc0, wA = hsel ? w1 : w0;
        float scB = hsel ? sc3 : sc2, wB = hsel ? w3 : w2;
        acc0.x = acc0.x * scA + wA * f0.x;
        acc0.y = acc0.y * scA + wA * f0.y;
        acc0.z = acc0.z * scA + wA * f0.z;
        acc0.w = acc0.w * scA + wA * f0.w;
        acc1.x = acc1.x * scB + wB * f1.x;
        acc1.y = acc1.y * scB + wB * f1.y;
        acc1.z = acc1.z * scB + wB * f1.z;
        acc1.w = acc1.w * scB + wB * f1.w;

        if (!have_next) break;
        a4 = a4n; f0 = f0n; f1 = f1n;
    }

    float sA = (hsel ? s1 : s0) + 1e-16f;
    float sB = (hsel ? s3 : s2) + 1e-16f;
    float4 b0 = *(const float4*)&bias[lane * 4];
    float4 b1 = *(const float4*)&bias[128 + lane * 4];
    float4 o0, o1;
    o0.x = fmaxf(acc0.x / sA + b0.x, 0.f);
    o0.y = fmaxf(acc0.y / sA + b0.y, 0.f);
    o0.z = fmaxf(acc0.z / sA + b0.z, 0.f);
    o0.w = fmaxf(acc0.w / sA + b0.w, 0.f);
    o1.x = fmaxf(acc1.x / sB + b1.x, 0.f);
    o1.y = fmaxf(acc1.y / sB + b1.y, 0.f);
    o1.z = fmaxf(acc1.z / sB + b1.z, 0.f);
    o1.w = fmaxf(acc1.w / sB + b1.w, 0.f);
    *(float4*)&out[(size_t)gw * 256 + lane * 4] = o0;
    *(float4*)&out[(size_t)gw * 256 + 128 + lane * 4] = o1;
}

// ---------------- aggregation H=1 (no relu): float2 per lane ---------------

__global__ void __launch_bounds__(256)
k_agg1(const float* __restrict__ hproj,
       const float* __restrict__ asrc, const float* __restrict__ adst,
       const int* __restrict__ off, const int* __restrict__ csr,
       const float* __restrict__ bias, float* __restrict__ out, int n) {
    int gw = (blockIdx.x * blockDim.x + threadIdx.x) >> 5;
    if (gw >= n) return;
    int lane = threadIdx.x & 31;

    float adh = adst[gw];
    float m = -1e30f, s = 0.f;
    float2 acc = make_float2(0.f, 0.f);

    int beg = off[gw], end = off[gw + 1];

    float av = asrc[gw];
    float2 f = *(const float2*)&hproj[(size_t)gw * 64 + lane * 2];

    for (int e = beg; ; e++) {
        bool have_next = e < end;
        int srcn = 0;
        float avn; float2 fn;
        if (have_next) {
            srcn = csr[e];
            avn = asrc[srcn];
            fn = *(const float2*)&hproj[(size_t)srcn * 64 + lane * 2];
        }

        float ev = av + adh; ev = ev > 0.f ? ev : 0.2f * ev;
        float nm = fmaxf(m, ev);
        float sc = __expf(m - nm);
        float w = __expf(ev - nm);
        s = s * sc + w;
        m = nm;
        acc.x = acc.x * sc + w * f.x;
        acc.y = acc.y * sc + w * f.y;

        if (!have_next) break;
        av = avn; f = fn;
    }

    float inv = 1.f / (s + 1e-16f);
    float2 o;
    o.x = acc.x * inv + bias[lane * 2];
    o.y = acc.y * inv + bias[lane * 2 + 1];
    *(float2*)&out[(size_t)gw * 64 + lane * 2] = o;
}

// ---------------- final MLP: 64 -> 32 (relu) -> 1, warp per node -----------

__global__ void __launch_bounds__(256)
k_mlp(const float* __restrict__ feat,
      const float* __restrict__ Wo1, const float* __restrict__ bo1,
      const float* __restrict__ Wo2, const float* __restrict__ bo2,
      float* __restrict__ out, int n) {
    int gw = (blockIdx.x * blockDim.x + threadIdx.x) >> 5;
    if (gw >= n) return;
    int lane = threadIdx.x & 31;
    float f0 = feat[(size_t)gw * 64 + lane];
    float f1 = feat[(size_t)gw * 64 + 32 + lane];
    float hid = bo1[lane];
    #pragma unroll
    for (int k = 0; k < 32; k++) {
        float xv = __shfl_sync(0xffffffffu, f0, k);
        hid += xv * Wo1[k * 32 + lane];
    }
    #pragma unroll
    for (int k = 0; k < 32; k++) {
        float xv = __shfl_sync(0xffffffffu, f1, k);
        hid += xv * Wo1[(32 + k) * 32 + lane];
    }
    hid = fmaxf(hid, 0.f);
    float p = hid * Wo2[lane];
    #pragma unroll
    for (int o = 16; o > 0; o >>= 1) p += __shfl_xor_sync(0xffffffffu, p, o);
    if (lane == 0) out[gw] = p + bo2[0];
}

// ---------------------------------------------------------------------------

extern "C" void kernel_launch(void* const* d_in, const int* in_sizes, int n_in,
                              void* d_out, int out_size) {
    const float* x     = (const float*)d_in[0];
    const float* W_emb = (const float*)d_in[1];
    const float* b_emb = (const float*)d_in[2];
    const float* W0    = (const float*)d_in[3];
    const float* as0   = (const float*)d_in[4];
    const float* ad0   = (const float*)d_in[5];
    const float* b0    = (const float*)d_in[6];
    const float* W1    = (const float*)d_in[7];
    const float* as1   = (const float*)d_in[8];
    const float* ad1   = (const float*)d_in[9];
    const float* b1    = (const float*)d_in[10];
    const float* W2    = (const float*)d_in[11];
    const float* as2   = (const float*)d_in[12];
    const float* ad2   = (const float*)d_in[13];
    const float* b2    = (const float*)d_in[14];
    const float* Wo1   = (const float*)d_in[15];
    const float* bo1   = (const float*)d_in[16];
    const float* Wo2   = (const float*)d_in[17];
    const float* bo2   = (const float*)d_in[18];
    const int*   ei    = (const int*)d_in[19];

    int n = in_sizes[0] / 128;
    int E = in_sizes[19] / 2;
    const int* esrc = ei;
    const int* edst = ei + E;

    float *featA, *featB, *proj, *asb, *adb;
    int *off, *cur, *bsum, *csr;
    __nv_bfloat16 *wth, *wtl;
    cudaGetSymbolAddress((void**)&featA, g_featA);
    cudaGetSymbolAddress((void**)&featB, g_featB);
    cudaGetSymbolAddress((void**)&proj,  g_proj);
    cudaGetSymbolAddress((void**)&asb,   g_as);
    cudaGetSymbolAddress((void**)&adb,   g_ad);
    cudaGetSymbolAddress((void**)&off,   g_off);
    cudaGetSymbolAddress((void**)&cur,   g_cur);
    cudaGetSymbolAddress((void**)&bsum,  g_bsum);
    cudaGetSymbolAddress((void**)&csr,   g_csr);
    cudaGetSymbolAddress((void**)&wth,   g_wt_hi);
    cudaGetSymbolAddress((void**)&wtl,   g_wt_lo);

    constexpr int SMEM64  = (2 * 128 * 36 + 2 * 64 * 36) * 4;   // 55296
    constexpr int SMEM128 = (2 * 128 * 36 + 2 * 128 * 36) * 4;  // 73728
    cudaFuncSetAttribute(k_mma_gemm<64, 0, true>,   cudaFuncAttributeMaxDynamicSharedMemorySize, SMEM64);
    cudaFuncSetAttribute(k_mma_gemm<128, 4, false>, cudaFuncAttributeMaxDynamicSharedMemorySize, SMEM128);
    cudaFuncSetAttribute(k_mma_gemm<64, 1, false>,  cudaFuncAttributeMaxDynamicSharedMemorySize, SMEM64);

    dim3 blk(256);
    int gemmBlocks = (n + 127) / 128;
    int warpBlocks = (n + 7) / 8;
    int nb = (n + 1023) / 1024;

    // ncu captures MY launch index 3 (harness issues ~2 launches first, -s 5).
    // Index 3 = proj0 big GEMM.

    // (0) embed W convert, (1) embed GEMM -> featA[n,64], (2) W0 convert,
    // (3) proj0 GEMM + fused alpha  <-- profile capture slot
    k_cvt_w<<<(128 * 64 + 255) / 256, blk>>>(W_emb, wth, wtl, 128, 64);
    k_mma_gemm<64, 0, true><<<dim3(gemmBlocks, 1), blk, SMEM64>>>(
        x, wth, wtl, b_emb, nullptr, nullptr, featA, nullptr, nullptr, n, 128, 64);
    k_cvt_w<<<(64 * 256 + 255) / 256, blk>>>(W0, wth, wtl, 64, 256);
    k_mma_gemm<128, 4, false><<<dim3(gemmBlocks, 2), blk, SMEM128>>>(
        featA, wth, wtl, nullptr, as0, ad0, proj, asb, adb, n, 64, 256);

    // (4-9) CSR build
    k_zero_int<<<(n + 1 + 255) / 256, 256>>>(off, n + 1);
    k_count_deg<<<(E + 255) / 256, 256>>>(edst, off, E);
    k_scan1<<<nb, 1024>>>(off, bsum, n);
    k_scan2<<<1, 32>>>(bsum, nb);
    k_scan3<<<(n + 255) / 256, 256>>>(off, bsum, cur, n, E);
    k_scatter<<<(E + 255) / 256, 256>>>(esrc, edst, cur, csr, E);

    // (10) agg0 -> featB[n,256]
    k_agg4<<<warpBlocks, blk>>>(proj, asb, adb, off, csr, b0, featB, n);

    // layer 1
    k_cvt_w<<<(256 * 256 + 255) / 256, blk>>>(W1, wth, wtl, 256, 256);
    k_mma_gemm<128, 4, false><<<dim3(gemmBlocks, 2), blk, SMEM128>>>(
        featB, wth, wtl, nullptr, as1, ad1, proj, asb, adb, n, 256, 256);
    k_agg4<<<warpBlocks, blk>>>(proj, asb, adb, off, csr, b1, featA, n);

    // layer 2 (H=1, no relu)
    k_cvt_w<<<(256 * 64 + 255) / 256, blk>>>(W2, wth, wtl, 256, 64);
    k_mma_gemm<64, 1, false><<<dim3(gemmBlocks, 1), blk, SMEM64>>>(
        featA, wth, wtl, nullptr, as2, ad2, proj, asb, adb, n, 256, 64);
    k_agg1<<<warpBlocks, blk>>>(proj, asb, adb, off, csr, b2, featB, n);

    // MLP tail -> d_out [n,1]
    k_mlp<<<warpBlocks, blk>>>(featB, Wo1, bo1, Wo2, bo2, (float*)d_out, n);
}